// round 2
// baseline (speedup 1.0000x reference)
#include <cuda_runtime.h>

#define N 512
#define ROWS_PER_BLOCK 4
#define NWARPS (N / 32)

// Closed form for the Givens-rotation chain (rotations on columns (i,i+1),
// applied for i = N-2 down to 0, theta index == i):
//   U[r][j]   = 0                                        for j > r+1
//   U[r][r+1] = s_r
//   U[r][j]   = c'_r * c_{j-1} * prod_{m=j}^{r-1} (-s_m) for j <= r
// with c_{-1} = 1 and c'_{N-1} = 1.
//
// Per block (4 rows starting at r0): thread j needs
//   T[j] = prod_{m=j}^{r0-1} (-s_m)   (1 if j >= r0)
// computed as a suffix-product scan of a[j] = (j < r0 ? -s_j : 1):
//   warp-level shuffle suffix scan (5 steps) + 16 warp totals combined by
//   warp 0 (4 shuffle steps). Only 2 __syncthreads total.
__global__ __launch_bounds__(N) void unitary_closed_form_kernel(
    const float* __restrict__ thetas,  // K = N-1 = 511 angles
    float* __restrict__ out)           // N x N row-major fp32
{
    __shared__ float sh_s[N];      // sin(theta_j), sh_s[N-1] = 0
    __shared__ float sh_c[N];      // cos(theta_j), sh_c[N-1] = 1
    __shared__ float shE[NWARPS];  // exclusive suffix product of warp totals

    const int j    = threadIdx.x;
    const int lane = j & 31;
    const int w    = j >> 5;
    const int r0   = blockIdx.x * ROWS_PER_BLOCK;

    float sj = 0.0f, cj = 1.0f;
    if (j < N - 1) {
        sincosf(thetas[j], &sj, &cj);
    }
    sh_s[j] = sj;
    sh_c[j] = cj;

    // a[j] = -s_j for j < r0, else 1. Suffix-product within warp:
    // after the loop, p = prod_{m=j}^{warp_end} a_m.
    float p = (j < r0) ? -sj : 1.0f;
    #pragma unroll
    for (int off = 1; off < 32; off <<= 1) {
        float v = __shfl_down_sync(0xffffffffu, p, off);
        if (lane + off < 32) p *= v;
    }

    // Warp totals (lane 0 of each warp holds its full-warp product) -> warp 0
    // computes the exclusive suffix product across the 16 warps.
    __shared__ float shW[NWARPS];
    if (lane == 0) shW[w] = p;
    __syncthreads();

    if (w == 0) {
        float q = (lane < NWARPS) ? shW[lane] : 1.0f;
        float pi = q;
        #pragma unroll
        for (int off = 1; off < NWARPS; off <<= 1) {
            float v = __shfl_down_sync(0xffffffffu, pi, off);
            if (lane + off < NWARPS) pi *= v;
        }
        // exclusive: E[w] = inclusive[w+1], E[last] = 1
        float e = __shfl_down_sync(0xffffffffu, pi, 1);
        if (lane >= NWARPS - 1) e = 1.0f;
        if (lane < NWARPS) shE[lane] = e;
    }
    __syncthreads();

    const float T = p * shE[w];  // prod_{m=j}^{r0-1} (-s_m)

    const float cm1   = (j > 0) ? sh_c[j - 1] : 1.0f;
    const float sprev = (j > 0) ? sh_s[j - 1] : 0.0f;
    float x = cm1 * T;

    float* row = out + (size_t)r0 * N + j;
    #pragma unroll
    for (int k = 0; k < ROWS_PER_BLOCK; ++k) {
        const int r = r0 + k;
        float val;
        if (j <= r) {
            val = sh_c[r] * x;   // sh_c[N-1] == 1 handles r = N-1
            x *= -sh_s[r];       // sh_s[N-1] == 0, x unused afterwards
        } else if (j == r + 1) {
            val = sprev;         // superdiagonal: s_r
        } else {
            val = 0.0f;
        }
        row[0] = val;            // coalesced across j
        row += N;
    }
}

extern "C" void kernel_launch(void* const* d_in, const int* in_sizes, int n_in,
                              void* d_out, int out_size) {
    (void)in_sizes; (void)n_in; (void)out_size;
    const float* thetas = (const float*)d_in[0];
    float* out = (float*)d_out;
    unitary_closed_form_kernel<<<N / ROWS_PER_BLOCK, N>>>(thetas, out);
}

// round 3
// speedup vs baseline: 1.0386x; 1.0386x over previous
#include <cuda_runtime.h>

#define N 512
#define ROWS_PER_BLOCK 4
#define NWARPS (N / 32)

// Closed form for the Givens-rotation chain (rotations on columns (i,i+1),
// applied for i = N-2 down to 0, theta index == i):
//   U[r][j]   = 0                                        for j > r+1
//   U[r][r+1] = s_r
//   U[r][j]   = c'_r * c_{j-1} * prod_{m=j}^{r-1} (-s_m) for j <= r
// with c_{-1} = 1 and c'_{N-1} = 1.
//
// Thread j of block b (rows r0..r0+3) needs T[j] = prod_{m=j}^{r0-1}(-s_m).
// Computed as: 5-step warp shuffle suffix scan + every warp redundantly
// combining the 16 warp totals in registers (4 shuffles + 1 broadcast).
// Exactly ONE __syncthreads in the whole kernel.
__global__ __launch_bounds__(N) void unitary_closed_form_kernel(
    const float* __restrict__ thetas,  // K = N-1 = 511 angles
    float* __restrict__ out)           // N x N row-major fp32
{
    __shared__ float sh_s[N];      // sin(theta_j), sh_s[N-1] = 0
    __shared__ float sh_c[N];      // cos(theta_j), sh_c[N-1] = 1
    __shared__ float shW[NWARPS];  // per-warp product of a[j]

    const int j    = threadIdx.x;
    const int lane = j & 31;
    const int w    = j >> 5;
    const int r0   = blockIdx.x * ROWS_PER_BLOCK;

    float sj = 0.0f, cj = 1.0f;
    if (j < N - 1) {
        __sincosf(thetas[j], &sj, &cj);   // MUFU fast path; norm-based rel_err
    }
    sh_s[j] = sj;
    sh_c[j] = cj;

    // a[j] = -s_j for j < r0, else 1. Warp suffix-product scan:
    // p = prod_{m=j}^{warp_end} a_m after 5 steps.
    float p = (j < r0) ? -sj : 1.0f;
    #pragma unroll
    for (int off = 1; off < 32; off <<= 1) {
        float v = __shfl_down_sync(0xffffffffu, p, off);
        if (lane + off < 32) p *= v;
    }
    if (lane == 0) shW[w] = p;

    __syncthreads();   // covers sh_s, sh_c, shW

    // Every warp combines the 16 warp totals redundantly (no warp-0 serialization).
    // t[lane] = prod_{m=lane}^{15} shW[m] for lane < 16.
    float t = (lane < NWARPS) ? shW[lane] : 1.0f;
    #pragma unroll
    for (int off = 1; off < NWARPS; off <<= 1) {
        float v = __shfl_down_sync(0xffffffffu, t, off);
        if (lane + off < NWARPS) t *= v;
    }
    // Exclusive term for this warp: E[w] = t[w+1], E[NWARPS-1] = 1.
    float e = __shfl_sync(0xffffffffu, t, (w + 1) & (NWARPS - 1));
    if (w == NWARPS - 1) e = 1.0f;

    const float T = p * e;   // prod_{m=j}^{r0-1} (-s_m)

    const float cm1   = (j > 0) ? sh_c[j - 1] : 1.0f;
    const float sprev = (j > 0) ? sh_s[j - 1] : 0.0f;
    float x = cm1 * T;

    // Row constants (broadcast LDS).
    float cr[ROWS_PER_BLOCK], sr[ROWS_PER_BLOCK];
    #pragma unroll
    for (int k = 0; k < ROWS_PER_BLOCK; ++k) {
        cr[k] = sh_c[r0 + k];
        sr[k] = sh_s[r0 + k];
    }

    float* row = out + (size_t)r0 * N + j;
    #pragma unroll
    for (int k = 0; k < ROWS_PER_BLOCK; ++k) {
        const int r = r0 + k;
        float val;
        if (j <= r) {
            val = cr[k] * x;     // sh_c[N-1] == 1 handles r = N-1
            x *= -sr[k];         // sh_s[N-1] == 0, x unused afterwards
        } else if (j == r + 1) {
            val = sprev;         // superdiagonal: s_r
        } else {
            val = 0.0f;
        }
        row[0] = val;            // coalesced across j
        row += N;
    }
}

extern "C" void kernel_launch(void* const* d_in, const int* in_sizes, int n_in,
                              void* d_out, int out_size) {
    (void)in_sizes; (void)n_in; (void)out_size;
    const float* thetas = (const float*)d_in[0];
    float* out = (float*)d_out;
    unitary_closed_form_kernel<<<N / ROWS_PER_BLOCK, N>>>(thetas, out);
}